// round 11
// baseline (speedup 1.0000x reference)
#include <cuda_runtime.h>
#include <cuda_bf16.h>
#include <cstdint>

// Problem constants
#define N_EMBED 512
#define DIMQ    64          // IN_MEM*OUT_MEM
#define NROWS   4096        // IN_G*OUT_G
#define KDIM    512
#define NDIM    512
#define BDIM    8192
#define QBLK2   (NROWS / 16)   // 256 quantize blocks (16 rows each)
#define XBLKS   2048           // xsplit blocks

// Scratch (no cudaMalloc allowed)
__device__ __nv_bfloat16  d_WtHi[NDIM * KDIM];    // W^T hi  [n][k]
__device__ __nv_bfloat16  d_WtLo[NDIM * KDIM];    // W^T lo  [n][k]
__device__ __nv_bfloat16  d_XHi[BDIM * KDIM];     // x hi    [m][k]
__device__ __nv_bfloat16  d_XLo[BDIM * KDIM];     // x lo    [m][k]
__device__ double         d_diff_blk[QBLK2];      // per-block diff partials

// ---------------------------------------------------------------------------
// helpers
// ---------------------------------------------------------------------------
__device__ __forceinline__ uint32_t smem_u32(const void* p) {
    uint32_t a;
    asm("{ .reg .u64 t; cvta.to.shared.u64 t, %1; cvt.u32.u64 %0, t; }" : "=r"(a) : "l"(p));
    return a;
}
__device__ __forceinline__ void split2(float a, float b, uint32_t& h, uint32_t& l) {
    __nv_bfloat16 ah = __float2bfloat16_rn(a);
    __nv_bfloat16 bh = __float2bfloat16_rn(b);
    __nv_bfloat16 al = __float2bfloat16_rn(a - __bfloat162float(ah));
    __nv_bfloat16 bl = __float2bfloat16_rn(b - __bfloat162float(bh));
    __nv_bfloat162 hv; hv.x = ah; hv.y = bh;
    __nv_bfloat162 lv; lv.x = al; lv.y = bl;
    h = *(uint32_t*)&hv; l = *(uint32_t*)&lv;
}
__device__ __forceinline__ void ldsm4(uint32_t* r, uint32_t addr) {
    asm volatile("ldmatrix.sync.aligned.m8n8.x4.shared.b16 {%0,%1,%2,%3}, [%4];"
                 : "=r"(r[0]), "=r"(r[1]), "=r"(r[2]), "=r"(r[3]) : "r"(addr));
}
__device__ __forceinline__ void mma16816(float* c, const uint32_t* a,
                                         uint32_t b0, uint32_t b1) {
    asm volatile("mma.sync.aligned.m16n8k16.row.col.f32.bf16.bf16.f32 "
                 "{%0,%1,%2,%3}, {%4,%5,%6,%7}, {%8,%9}, {%0,%1,%2,%3};"
                 : "+f"(c[0]), "+f"(c[1]), "+f"(c[2]), "+f"(c[3])
                 : "r"(a[0]), "r"(a[1]), "r"(a[2]), "r"(a[3]), "r"(b0), "r"(b1));
}

// ---------------------------------------------------------------------------
// fused pre-pass: blocks [0,256) = quantize (16 rows each);
//                 blocks [256,2304) = xsplit (x fp32 -> bf16 hi/lo planes).
// (unchanged from R10 passing version)
// ---------------------------------------------------------------------------
__global__ __launch_bounds__(256) void prepass_kernel(
    const float* __restrict__ w,        // [4096,64] flat
    const float* __restrict__ embed,    // [64,512]
    const float* __restrict__ x)        // [8192,512]
{
    const int tid = threadIdx.x;

    if (blockIdx.x >= QBLK2) {
        const size_t base = ((size_t)(blockIdx.x - QBLK2) * 256 + tid) * 8;
        float4 v0 = __ldg((const float4*)(x + base));
        float4 v1 = __ldg((const float4*)(x + base + 4));
        uint32_t h[4], l[4];
        split2(v0.x, v0.y, h[0], l[0]);
        split2(v0.z, v0.w, h[1], l[1]);
        split2(v1.x, v1.y, h[2], l[2]);
        split2(v1.z, v1.w, h[3], l[3]);
        *(uint4*)&d_XHi[base] = make_uint4(h[0], h[1], h[2], h[3]);
        *(uint4*)&d_XLo[base] = make_uint4(l[0], l[1], l[2], l[3]);
        return;
    }

    __shared__ float  ws[16][DIMQ];
    __shared__ double blk_diff[8];

    const int ty  = tid >> 5;
    const int tx  = tid & 31;
    const int row0 = blockIdx.x * 16;

    {
        const int r = tid >> 4;
        const int c = (tid & 15) * 4;
        *(float4*)&ws[r][c] = __ldg((const float4*)(w + (size_t)(row0 + r) * DIMQ + c));
    }
    __syncthreads();

    float acc[2][16];
    float e2acc[16];
    #pragma unroll
    for (int c = 0; c < 16; ++c) e2acc[c] = 0.f;
    #pragma unroll
    for (int r = 0; r < 2; ++r)
        #pragma unroll
        for (int c = 0; c < 16; ++c) acc[r][c] = 0.f;

    #pragma unroll 4
    for (int d = 0; d < DIMQ; ++d) {
        float e[16];
        #pragma unroll
        for (int g = 0; g < 4; ++g)
            *(float4*)&e[g * 4] = __ldg((const float4*)(embed + d * N_EMBED + g * 128 + tx * 4));
        float wv0 = ws[ty * 2][d];
        float wv1 = ws[ty * 2 + 1][d];
        #pragma unroll
        for (int c = 0; c < 16; ++c) {
            e2acc[c]  += e[c] * e[c];
            acc[0][c] += wv0 * e[c];
            acc[1][c] += wv1 * e[c];
        }
    }

    float diff_local = 0.f;
    #pragma unroll
    for (int r = 0; r < 2; ++r) {
        float best = 3.4e38f;
        int   bidx = 0;
        #pragma unroll
        for (int g = 0; g < 4; ++g)
            #pragma unroll
            for (int j = 0; j < 4; ++j) {
                int c = g * 128 + tx * 4 + j;
                float s = e2acc[g * 4 + j] - 2.f * acc[r][g * 4 + j];
                if (s < best) { best = s; bidx = c; }
            }
        #pragma unroll
        for (int off = 16; off >= 1; off >>= 1) {
            float ob = __shfl_xor_sync(0xffffffffu, best, off);
            int   oi = __shfl_xor_sync(0xffffffffu, bidx, off);
            if (ob < best || (ob == best && oi < bidx)) { best = ob; bidx = oi; }
        }
        const int rl  = ty * 2 + r;
        const int row = row0 + rl;
        const int ig = row >> 6;
        const int og = row & 63;
        const int om = tx & 7;
        const int i0 = (tx >> 3) * 2;
        const int d0 = i0 * 8 + om;
        const int d1 = d0 + 8;
        float q0 = __ldg(embed + d0 * N_EMBED + bidx);
        float q1 = __ldg(embed + d1 * N_EMBED + bidx);
        float w0 = ws[rl][d0], w1 = ws[rl][d1];
        float df0 = q0 - w0, df1 = q1 - w1;
        diff_local += df0 * df0 + df1 * df1;
        uint32_t h, l;
        split2(q0, q1, h, l);
        const size_t off_nk = (size_t)(og * 8 + om) * KDIM + ig * 8 + i0;
        *(uint32_t*)&d_WtHi[off_nk] = h;
        *(uint32_t*)&d_WtLo[off_nk] = l;
    }

    #pragma unroll
    for (int off = 16; off >= 1; off >>= 1)
        diff_local += __shfl_xor_sync(0xffffffffu, diff_local, off);
    if (tx == 0) blk_diff[ty] = (double)diff_local;
    __syncthreads();
    if (tid == 0) {
        double s = 0.0;
        #pragma unroll
        for (int i = 0; i < 8; ++i) s += blk_diff[i];
        d_diff_blk[blockIdx.x] = s;
    }
}

// ---------------------------------------------------------------------------
// HMMA GEMM v3: C = x @ W via bf16 split (3 products), fp32 accum.
// CTA 128x128, 8 warps (warp tile 32x64), BK=32, 16 chunks.
// Smem layout: per stage, A region (128 rows x 128B: [hi 64B | lo 64B]) then
// W region (same). XOR swizzle (chunk ^= row&7) -> conflict-free, no padding.
// Stage = 32KB; 3-stage cp.async pipeline with wait_group 1. 2 CTAs/SM.
// ---------------------------------------------------------------------------
#define BK      32
#define NCH     (KDIM / BK)         // 16
#define WREG    16384               // W region offset within stage
#define STAGEB  32768
#define NSTG    3
#define SMEMB   (NSTG * STAGEB)     // 98304

__global__ __launch_bounds__(256, 2) void gemm_mma_kernel(
    float* __restrict__ C,          // res [B,512] (+ diff scalar)
    long n_res, long out_total)
{
    extern __shared__ char smem[];
    __shared__ double sdiff[8];
    const uint32_t sb = smem_u32(smem);
    const int tid  = threadIdx.x;
    const int lane = tid & 31;
    const int wid  = tid >> 5;
    const int m0 = blockIdx.y * 128;
    const int n0 = blockIdx.x * 128;
    const int wm = (wid & 3) * 32;
    const int wn = (wid >> 2) * 64;

    // parallel diff reduction on CTA (0,0)
    if (blockIdx.x == 0 && blockIdx.y == 0 && out_total > n_res) {
        double v = d_diff_blk[tid];                 // QBLK2 == 256 == blockDim
        #pragma unroll
        for (int off = 16; off >= 1; off >>= 1)
            v += __shfl_xor_sync(0xffffffffu, v, off);
        if (lane == 0) sdiff[wid] = v;
        __syncthreads();
        if (tid == 0) {
            double s = 0.0;
            #pragma unroll
            for (int i = 0; i < 8; ++i) s += sdiff[i];
            C[n_res] = (float)(s * (1.0 / (double)(NROWS * DIMQ)));
        }
    }

    // ---- cp.async thread mapping: row = tid>>1 (0..127), plane = tid&1 ----
    const int crow   = tid >> 1;
    const int cplane = tid & 1;
    const __nv_bfloat16* aG = (cplane ? d_XLo  : d_XHi ) + (size_t)(m0 + crow) * KDIM;
    const __nv_bfloat16* wG = (cplane ? d_WtLo : d_WtHi) + (size_t)(n0 + crow) * KDIM;
    // swizzled store offsets for the 4 16B chunks (identical for A and W regions)
    uint32_t stOff[4];
    #pragma unroll
    for (int j = 0; j < 4; ++j) {
        uint32_t rel = (uint32_t)crow * 128 + (uint32_t)cplane * 64 + j * 16;
        stOff[j] = rel ^ (((uint32_t)(crow & 7)) << 4);
    }

    // ---- ldmatrix fragment base addresses (region-relative, swizzled) ----
    // A: rows wm + mt*16 + (lane&15); chunk bit = lane>>4
    uint32_t aAddr[2];
    #pragma unroll
    for (int mt = 0; mt < 2; ++mt) {
        int r = wm + mt * 16 + (lane & 15);
        aAddr[mt] = (uint32_t)r * 128 + ((uint32_t)((r & 7) ^ (lane >> 4)) << 4);
    }
    // W: rows wn + p*16 + (lane>>4)*8 + (lane&7); chunk bit = (lane>>3)&1
    uint32_t bAddr[4];
    #pragma unroll
    for (int p = 0; p < 4; ++p) {
        int r = wn + p * 16 + ((lane >> 4) * 8) + (lane & 7);
        bAddr[p] = WREG + (uint32_t)r * 128
                 + ((uint32_t)((r & 7) ^ ((lane >> 3) & 1)) << 4);
    }

    float acc[2][8][4];
    #pragma unroll
    for (int mt = 0; mt < 2; ++mt)
        #pragma unroll
        for (int nt = 0; nt < 8; ++nt)
            #pragma unroll
            for (int q = 0; q < 4; ++q) acc[mt][nt][q] = 0.f;

    #define CPALL(kc, stage) do {                                                 \
        uint32_t _sbase = sb + (stage) * STAGEB;                                  \
        const char* _as = (const char*)(aG + (kc) * BK);                          \
        const char* _ws = (const char*)(wG + (kc) * BK);                          \
        _Pragma("unroll")                                                         \
        for (int _j = 0; _j < 4; ++_j)                                            \
            asm volatile("cp.async.cg.shared.global [%0], [%1], 16;"              \
                         :: "r"(_sbase + stOff[_j]), "l"(_as + _j * 16) : "memory"); \
        _Pragma("unroll")                                                         \
        for (int _j = 0; _j < 4; ++_j)                                            \
            asm volatile("cp.async.cg.shared.global [%0], [%1], 16;"              \
                         :: "r"(_sbase + WREG + stOff[_j]), "l"(_ws + _j * 16) : "memory"); \
        asm volatile("cp.async.commit_group;" ::: "memory");                      \
    } while (0)

    #define COMPUTE(stage) do {                                                   \
        uint32_t _S = sb + (stage) * STAGEB;                                      \
        _Pragma("unroll")                                                         \
        for (int _ks = 0; _ks < 2; ++_ks) {                                       \
            const uint32_t _ko = (uint32_t)_ks << 5;                              \
            uint32_t _ahi[2][4], _alo[2][4], _bf[4][4];                           \
            _Pragma("unroll")                                                     \
            for (int _mt = 0; _mt < 2; ++_mt) {                                   \
                ldsm4(_ahi[_mt], _S + (aAddr[_mt] ^ _ko));                        \
                ldsm4(_alo[_mt], _S + (aAddr[_mt] ^ (_ko | 0x40u)));              \
            }                                                                     \
            _Pragma("unroll")                                                     \
            for (int _p = 0; _p < 4; ++_p)                                        \
                ldsm4(_bf[_p], _S + (bAddr[_p] ^ _ko));                           \
            _Pragma("unroll")                                                     \
            for (int _mt = 0; _mt < 2; ++_mt)                                     \
                _Pragma("unroll")                                                 \
                for (int _nt = 0; _nt < 8; ++_nt) {                               \
                    uint32_t _b0 = _bf[_nt >> 1][(_nt & 1) * 2];                  \
                    uint32_t _b1 = _bf[_nt >> 1][(_nt & 1) * 2 + 1];              \
                    mma16816(acc[_mt][_nt], _ahi[_mt], _b0, _b1);                 \
                    mma16816(acc[_mt][_nt], _alo[_mt], _b0, _b1);                 \
                }                                                                 \
            _Pragma("unroll")                                                     \
            for (int _p = 0; _p < 4; ++_p)                                        \
                ldsm4(_bf[_p], _S + (bAddr[_p] ^ (_ko | 0x40u)));                 \
            _Pragma("unroll")                                                     \
            for (int _mt = 0; _mt < 2; ++_mt)                                     \
                _Pragma("unroll")                                                 \
                for (int _nt = 0; _nt < 8; ++_nt)                                 \
                    mma16816(acc[_mt][_nt], _ahi[_mt],                            \
                             _bf[_nt >> 1][(_nt & 1) * 2],                        \
                             _bf[_nt >> 1][(_nt & 1) * 2 + 1]);                   \
        }                                                                         \
    } while (0)

    // ---- 3-stage pipeline ----
    CPALL(0, 0);
    CPALL(1, 1);

    for (int kc = 0; kc < NCH; ++kc) {
        const int st = kc % NSTG;
        if (kc + 1 < NCH)
            asm volatile("cp.async.wait_group 1;" ::: "memory");
        else
            asm volatile("cp.async.wait_group 0;" ::: "memory");
        __syncthreads();
        if (kc + 2 < NCH) CPALL(kc + 2, (kc + 2) % NSTG);
        COMPUTE(st);
    }

    // ---- epilogue ----
    #pragma unroll
    for (int mt = 0; mt < 2; ++mt) {
        int row = m0 + wm + mt * 16 + (lane >> 2);
        #pragma unroll
        for (int nt = 0; nt < 8; ++nt) {
            int col = n0 + wn + nt * 8 + (lane & 3) * 2;
            *(float2*)&C[(size_t)row * NDIM + col] =
                make_float2(acc[mt][nt][0], acc[mt][nt][1]);
            *(float2*)&C[(size_t)(row + 8) * NDIM + col] =
                make_float2(acc[mt][nt][2], acc[mt][nt][3]);
        }
    }
}

// ---------------------------------------------------------------------------
// launch: 2 kernels
// ---------------------------------------------------------------------------
extern "C" void kernel_launch(void* const* d_in, const int* in_sizes, int n_in,
                              void* d_out, int out_size) {
    const float* x      = (const float*)d_in[0];
    const float* weight = (const float*)d_in[1];
    const float* embed  = (const float*)d_in[2];
    float* out = (float*)d_out;

    const int b = in_sizes[0] / KDIM;              // 8192

    prepass_kernel<<<QBLK2 + XBLKS, 256>>>(weight, embed, x);

    static int smem_set = 0;
    if (!smem_set) {
        cudaFuncSetAttribute(gemm_mma_kernel,
                             cudaFuncAttributeMaxDynamicSharedMemorySize, SMEMB);
        smem_set = 1;
    }
    dim3 grid(NDIM / 128, b / 128);                // (4, 64)
    gemm_mma_kernel<<<grid, 256, SMEMB>>>(out, (long)b * NDIM, (long)out_size);
}

// round 13
// speedup vs baseline: 1.6972x; 1.6972x over previous
#include <cuda_runtime.h>
#include <cuda_fp16.h>
#include <cstdint>

// Problem constants
#define N_EMBED 512
#define DIMQ    64          // IN_MEM*OUT_MEM
#define NROWS   4096        // IN_G*OUT_G
#define KDIM    512
#define NDIM    512
#define BDIM    8192
#define QBLK2   (NROWS / 16)   // 256 quantize blocks (16 rows each)
#define XBLKS   2048           // xsplit blocks

// Scratch (no cudaMalloc allowed)
__device__ __half   d_WtH[NDIM * KDIM];     // W^T fp16 [n][k]
__device__ __half   d_XH[BDIM * KDIM];      // x   fp16 [m][k]
__device__ double   d_diff_blk[QBLK2];      // per-block diff partials

// ---------------------------------------------------------------------------
// helpers
// ---------------------------------------------------------------------------
__device__ __forceinline__ uint32_t smem_u32(const void* p) {
    uint32_t a;
    asm("{ .reg .u64 t; cvta.to.shared.u64 t, %1; cvt.u32.u64 %0, t; }" : "=r"(a) : "l"(p));
    return a;
}
__device__ __forceinline__ uint32_t pack_h2(float a, float b) {
    __half2 v; v.x = __float2half_rn(a); v.y = __float2half_rn(b);
    return *(uint32_t*)&v;
}
__device__ __forceinline__ void ldsm4(uint32_t* r, uint32_t addr) {
    asm volatile("ldmatrix.sync.aligned.m8n8.x4.shared.b16 {%0,%1,%2,%3}, [%4];"
                 : "=r"(r[0]), "=r"(r[1]), "=r"(r[2]), "=r"(r[3]) : "r"(addr));
}
__device__ __forceinline__ void mma16816(float* c, const uint32_t* a,
                                         uint32_t b0, uint32_t b1) {
    asm volatile("mma.sync.aligned.m16n8k16.row.col.f32.f16.f16.f32 "
                 "{%0,%1,%2,%3}, {%4,%5,%6,%7}, {%8,%9}, {%0,%1,%2,%3};"
                 : "+f"(c[0]), "+f"(c[1]), "+f"(c[2]), "+f"(c[3])
                 : "r"(a[0]), "r"(a[1]), "r"(a[2]), "r"(a[3]), "r"(b0), "r"(b1));
}

// ---------------------------------------------------------------------------
// fused pre-pass: blocks [0,256) = quantize (16 rows each);
//                 blocks [256,2304) = xconvert (x fp32 -> fp16 plane).
// ---------------------------------------------------------------------------
__global__ __launch_bounds__(256) void prepass_kernel(
    const float* __restrict__ w,        // [4096,64] flat
    const float* __restrict__ embed,    // [64,512]
    const float* __restrict__ x)        // [8192,512]
{
    const int tid = threadIdx.x;

    if (blockIdx.x >= QBLK2) {
        // ---- x convert path: 8 floats -> 8 fp16 per thread ----
        const size_t base = ((size_t)(blockIdx.x - QBLK2) * 256 + tid) * 8;
        float4 v0 = __ldg((const float4*)(x + base));
        float4 v1 = __ldg((const float4*)(x + base + 4));
        uint4 o;
        o.x = pack_h2(v0.x, v0.y);
        o.y = pack_h2(v0.z, v0.w);
        o.z = pack_h2(v1.x, v1.y);
        o.w = pack_h2(v1.z, v1.w);
        *(uint4*)&d_XH[base] = o;
        return;
    }

    // ---- quantize path: 16 rows, thread = 2 rows x 16 codes ----
    __shared__ float  ws[16][DIMQ];
    __shared__ double blk_diff[8];

    const int ty  = tid >> 5;
    const int tx  = tid & 31;
    const int row0 = blockIdx.x * 16;

    {
        const int r = tid >> 4;
        const int c = (tid & 15) * 4;
        *(float4*)&ws[r][c] = __ldg((const float4*)(w + (size_t)(row0 + r) * DIMQ + c));
    }
    __syncthreads();

    float acc[2][16];
    float e2acc[16];
    #pragma unroll
    for (int c = 0; c < 16; ++c) e2acc[c] = 0.f;
    #pragma unroll
    for (int r = 0; r < 2; ++r)
        #pragma unroll
        for (int c = 0; c < 16; ++c) acc[r][c] = 0.f;

    #pragma unroll 4
    for (int d = 0; d < DIMQ; ++d) {
        float e[16];
        #pragma unroll
        for (int g = 0; g < 4; ++g)
            *(float4*)&e[g * 4] = __ldg((const float4*)(embed + d * N_EMBED + g * 128 + tx * 4));
        float wv0 = ws[ty * 2][d];
        float wv1 = ws[ty * 2 + 1][d];
        #pragma unroll
        for (int c = 0; c < 16; ++c) {
            e2acc[c]  += e[c] * e[c];
            acc[0][c] += wv0 * e[c];
            acc[1][c] += wv1 * e[c];
        }
    }

    float diff_local = 0.f;
    #pragma unroll
    for (int r = 0; r < 2; ++r) {
        float best = 3.4e38f;
        int   bidx = 0;
        #pragma unroll
        for (int g = 0; g < 4; ++g)
            #pragma unroll
            for (int j = 0; j < 4; ++j) {
                int c = g * 128 + tx * 4 + j;           // ascending within thread
                float s = e2acc[g * 4 + j] - 2.f * acc[r][g * 4 + j];
                if (s < best) { best = s; bidx = c; }   // strict < keeps lowest c
            }
        #pragma unroll
        for (int off = 16; off >= 1; off >>= 1) {
            float ob = __shfl_xor_sync(0xffffffffu, best, off);
            int   oi = __shfl_xor_sync(0xffffffffu, bidx, off);
            if (ob < best || (ob == best && oi < bidx)) { best = ob; bidx = oi; }
        }
        // all lanes agree on bidx for this row
        const int rl  = ty * 2 + r;
        const int row = row0 + rl;
        const int ig = row >> 6;
        const int og = row & 63;
        const int om = tx & 7;
        const int i0 = (tx >> 3) * 2;
        const int d0 = i0 * 8 + om;          // k = ig*8 + i0
        const int d1 = d0 + 8;               // k = ig*8 + i0 + 1
        float q0 = __ldg(embed + d0 * N_EMBED + bidx);
        float q1 = __ldg(embed + d1 * N_EMBED + bidx);
        float w0 = ws[rl][d0], w1 = ws[rl][d1];
        float df0 = q0 - w0, df1 = q1 - w1;
        diff_local += df0 * df0 + df1 * df1;
        const size_t off_nk = (size_t)(og * 8 + om) * KDIM + ig * 8 + i0;
        *(uint32_t*)&d_WtH[off_nk] = pack_h2(q0, q1);
    }

    #pragma unroll
    for (int off = 16; off >= 1; off >>= 1)
        diff_local += __shfl_xor_sync(0xffffffffu, diff_local, off);
    if (tx == 0) blk_diff[ty] = (double)diff_local;
    __syncthreads();
    if (tid == 0) {
        double s = 0.0;
        #pragma unroll
        for (int i = 0; i < 8; ++i) s += blk_diff[i];
        d_diff_blk[blockIdx.x] = s;
    }
}

// ---------------------------------------------------------------------------
// HMMA GEMM v4: C = x @ W, single fp16 product, fp32 accum.
// CTA 128x128, 8 warps (warp tile 32x64), BK=64 (128B rows), 8 chunks.
// Smem: per stage A region (128 rows x 128B) then W region (same), XOR
// swizzle (16B unit ^= row&7). Stage = 32KB; 3-stage cp.async pipeline,
// wait_group 1. 2 CTAs/SM. CTA(0,0) reduces diff partials in parallel.
// ---------------------------------------------------------------------------
#define BK      64
#define NCH     (KDIM / BK)         // 8
#define WREG    16384               // W region offset within stage
#define STAGEB  32768
#define NSTG    3
#define SMEMB   (NSTG * STAGEB)     // 98304

__global__ __launch_bounds__(256, 2) void gemm_mma_kernel(
    float* __restrict__ C,          // res [B,512] (+ diff scalar)
    long n_res, long out_total)
{
    extern __shared__ char smem[];
    __shared__ double sdiff[8];
    const uint32_t sb = smem_u32(smem);
    const int tid  = threadIdx.x;
    const int lane = tid & 31;
    const int wid  = tid >> 5;
    const int m0 = blockIdx.y * 128;
    const int n0 = blockIdx.x * 128;
    const int wm = (wid & 3) * 32;
    const int wn = (wid >> 2) * 64;

    // parallel diff reduction on CTA (0,0)
    if (blockIdx.x == 0 && blockIdx.y == 0 && out_total > n_res) {
        double v = d_diff_blk[tid];                 // QBLK2 == 256 == blockDim
        #pragma unroll
        for (int off = 16; off >= 1; off >>= 1)
            v += __shfl_xor_sync(0xffffffffu, v, off);
        if (lane == 0) sdiff[wid] = v;
        __syncthreads();
        if (tid == 0) {
            double s = 0.0;
            #pragma unroll
            for (int i = 0; i < 8; ++i) s += sdiff[i];
            C[n_res] = (float)(s * (1.0 / (double)(NROWS * DIMQ)));
        }
    }

    // ---- cp.async mapping: row = tid>>1 (0..127), half-row = tid&1 (64B) ----
    const int crow  = tid >> 1;
    const int chalf = tid & 1;
    const __half* aG = d_XH  + (size_t)(m0 + crow) * KDIM + chalf * 32;
    const __half* wG = d_WtH + (size_t)(n0 + crow) * KDIM + chalf * 32;
    uint32_t stOff[4];
    #pragma unroll
    for (int j = 0; j < 4; ++j) {
        uint32_t rel = (uint32_t)crow * 128 + (uint32_t)chalf * 64 + j * 16;
        stOff[j] = rel ^ (((uint32_t)(crow & 7)) << 4);
    }

    // ---- ldmatrix fragment base addresses (region-relative, swizzled) ----
    uint32_t aAddr[2];
    #pragma unroll
    for (int mt = 0; mt < 2; ++mt) {
        int r = wm + mt * 16 + (lane & 15);
        aAddr[mt] = (uint32_t)r * 128 + ((uint32_t)((r & 7) ^ (lane >> 4)) << 4);
    }
    uint32_t bAddr[4];
    #pragma unroll
    for (int p = 0; p < 4; ++p) {
        int r = wn + p * 16 + ((lane >> 4) * 8) + (lane & 7);
        bAddr[p] = WREG + (uint32_t)r * 128
                 + ((uint32_t)((r & 7) ^ ((lane >> 3) & 1)) << 4);
    }

    float acc[2][8][4];
    #pragma unroll
    for (int mt = 0; mt < 2; ++mt)
        #pragma unroll
        for (int nt = 0; nt < 8; ++nt)
            #pragma unroll
            for (int q = 0; q < 4; ++q) acc[mt][nt][q] = 0.f;

    #define CPALL(kc, stage) do {                                                 \
        uint32_t _sbase = sb + (stage) * STAGEB;                                  \
        const char* _as = (const char*)(aG + (kc) * BK);                          \
        const char* _ws = (const char*)(wG + (kc) * BK);                          \
        _Pragma("unroll")                                                         \
        for (int _j = 0; _j < 4; ++_j)                                            \
            asm volatile("cp.async.cg.shared.global [%0], [%1], 16;"              \
                         :: "r"(_sbase + stOff[_j]), "l"(_as + _j * 16) : "memory"); \
        _Pragma("unroll")                                                         \
        for (int _j = 0; _j < 4; ++_j)                                            \
            asm volatile("cp.async.cg.shared.global [%0], [%1], 16;"              \
                         :: "r"(_sbase + WREG + stOff[_j]), "l"(_ws + _j * 16) : "memory"); \
        asm volatile("cp.async.commit_group;" ::: "memory");                      \
    } while (0)

    #define COMPUTE(stage) do {                                                   \
        uint32_t _S = sb + (stage) * STAGEB;                                      \
        _Pragma("unroll")                                                         \
        for (int _ks = 0; _ks < 4; ++_ks) {                                       \
            const uint32_t _ko = (uint32_t)_ks << 5;                              \
            uint32_t _af[2][4], _bf[4][4];                                        \
            _Pragma("unroll")                                                     \
            for (int _mt = 0; _mt < 2; ++_mt)                                     \
                ldsm4(_af[_mt], _S + (aAddr[_mt] ^ _ko));                         \
            _Pragma("unroll")                                                     \
            for (int _p = 0; _p < 4; ++_p)                                        \
                ldsm4(_bf[_p], _S + (bAddr[_p] ^ _ko));                           \
            _Pragma("unroll")                                                     \
            for (int _mt = 0; _mt < 2; ++_mt)                                     \
                _Pragma("unroll")                                                 \
                for (int _nt = 0; _nt < 8; ++_nt)                                 \
                    mma16816(acc[_mt][_nt], _af[_mt],                             \
                             _bf[_nt >> 1][(_nt & 1) * 2],                        \
                             _bf[_nt >> 1][(_nt & 1) * 2 + 1]);                   \
        }                                                                         \
    } while (0)

    // ---- 3-stage pipeline over 8 chunks ----
    CPALL(0, 0);
    CPALL(1, 1);

    for (int kc = 0; kc < NCH; ++kc) {
        const int st = kc % NSTG;
        if (kc + 1 < NCH)
            asm volatile("cp.async.wait_group 1;" ::: "memory");
        else
            asm volatile("cp.async.wait_group 0;" ::: "memory");
        __syncthreads();
        if (kc + 2 < NCH) CPALL(kc + 2, (kc + 2) % NSTG);
        COMPUTE(st);
    }

    // ---- epilogue ----
    #pragma unroll
    for (int mt = 0; mt < 2; ++mt) {
        int row = m0 + wm + mt * 16 + (lane >> 2);
        #pragma unroll
        for (int nt = 0; nt < 8; ++nt) {
            int col = n0 + wn + nt * 8 + (lane & 3) * 2;
            *(float2*)&C[(size_t)row * NDIM + col] =
                make_float2(acc[mt][nt][0], acc[mt][nt][1]);
            *(float2*)&C[(size_t)(row + 8) * NDIM + col] =
                make_float2(acc[mt][nt][2], acc[mt][nt][3]);
        }
    }
}

// ---------------------------------------------------------------------------
// launch: 2 kernels
// ---------------------------------------------------------------------------
extern "C" void kernel_launch(void* const* d_in, const int* in_sizes, int n_in,
                              void* d_out, int out_size) {
    const float* x      = (const float*)d_in[0];
    const float* weight = (const float*)d_in[1];
    const float* embed  = (const float*)d_in[2];
    float* out = (float*)d_out;

    const int b = in_sizes[0] / KDIM;              // 8192

    prepass_kernel<<<QBLK2 + XBLKS, 256>>>(weight, embed, x);

    static int smem_set = 0;
    if (!smem_set) {
        cudaFuncSetAttribute(gemm_mma_kernel,
                             cudaFuncAttributeMaxDynamicSharedMemorySize, SMEMB);
        smem_set = 1;
    }
    dim3 grid(NDIM / 128, b / 128);                // (4, 64)
    gemm_mma_kernel<<<grid, 256, SMEMB>>>(out, (long)b * NDIM, (long)out_size);
}